// round 1
// baseline (speedup 1.0000x reference)
#include <cuda_runtime.h>

// NaturalCubicSplinePotential — GB300 sm_103a
//
// Strategy:
//  K1 coef_kernel : 8x128 natural-cubic tridiagonal solve (Thomas), then build a
//                   PADDED per-marginal table of 256 intervals of u-rescaled
//                   coefficients (u = fractional part of t, t = (x+4)*127/8 + 64).
//                   Pad intervals (outside [0,126]) hold the exactly re-centered
//                   extrapolation cubic of the clamped boundary interval, so the
//                   hot loop needs NO clamping.
//  K2 eval_kernel : 1024 blocks x 256 threads, single wave. Each block owns a
//                   contiguous 16384-element chunk (1/4 of a (bs,f) slab → one
//                   marginal per block). Per element: 1 FFMA + F2I + I2F + FADD +
//                   LDS.128 + 3 FFMA + FADD. Block partial sums -> g_part.
//  K3 reduce      : deterministic tree reduce of 1024 partials -> d_out[0].

#define NM 8
#define NN 128
#define TABN 256          // padded table entries per marginal
#define PADL 64           // pad below interval 0
#define EVAL_BLOCKS 1024
#define F4_PER_BLOCK 4096 // 16384 elements per block
#define NTHREADS 256

__device__ float4 g_tab[NM][TABN];
__device__ float  g_part[EVAL_BLOCKS];

// ---------------------------------------------------------------------------
// K1: spline coefficients + padded table
// ---------------------------------------------------------------------------
__global__ void coef_kernel(const float* __restrict__ nodal)
{
    __shared__ float ysh[NM][NN];
    __shared__ float csh[NM][NN];
    __shared__ float zsh[NM][NN];
    __shared__ float invb[NN];

    const int tid = threadIdx.x;

    // load nodal values (8 x 128)
    for (int e = tid; e < NM * NN; e += NTHREADS)
        ysh[e >> 7][e & 127] = nodal[e];
    __syncthreads();

    // reciprocal pivots of the [1,4,1] interior system (same for all marginals)
    if (tid == 0) {
        float ib = 0.25f;
        invb[1] = ib;
        for (int i = 2; i <= 126; ++i) {
            ib = 1.0f / (4.0f - ib);
            invb[i] = ib;
        }
    }
    __syncthreads();

    const float h      = 8.0f / 127.0f;
    const float inv_h2 = (127.0f / 8.0f) * (127.0f / 8.0f);

    // Thomas solve per marginal (8 threads, serial sweeps)
    if (tid < NM) {
        const int m = tid;
        // forward sweep: z[i] = r[i] - invb[i-1]*z[i-1]
        float zp = 3.0f * (ysh[m][0] - 2.0f * ysh[m][1] + ysh[m][2]) * inv_h2;
        zsh[m][1] = zp;
        for (int i = 2; i <= 126; ++i) {
            float r = 3.0f * (ysh[m][i - 1] - 2.0f * ysh[m][i] + ysh[m][i + 1]) * inv_h2;
            zp = r - invb[i - 1] * zp;
            zsh[m][i] = zp;
        }
        // backward sweep
        csh[m][0]   = 0.0f;
        csh[m][127] = 0.0f;
        float cn = zsh[m][126] * invb[126];
        csh[m][126] = cn;
        for (int i = 125; i >= 1; --i) {
            cn = (zsh[m][i] - cn) * invb[i];
            csh[m][i] = cn;
        }
    }
    __syncthreads();

    // Build padded, u-rescaled table.
    // In-range interval k: P(u) = a + B u + C u^2 + D u^3 with u = (x - node_k)/h
    //   a = y_k
    //   B = b*h = (y_{k+1}-y_k) - h^2 (2 c_k + c_{k+1})/3
    //   C = c_k h^2
    //   D = d*h^3 = (c_{k+1}-c_k) h^2 / 3
    // Pad entry with true interval i (clamped to k): shift by Delta = i-k:
    //   a' = a + B*D + C*D^2 + D*D^3 ; b' = B + 2C*Delta + 3D*Delta^2 ;
    //   c' = C + 3D*Delta ; d' = D
    const float h2 = h * h;
    for (int e = tid; e < NM * TABN; e += NTHREADS) {
        const int m  = e >> 8;
        const int j  = e & 255;
        const int it = j - PADL;
        const int k  = min(max(it, 0), 126);
        const float dlt = (float)(it - k);

        const float a  = ysh[m][k];
        const float c0 = csh[m][k];
        const float c1 = csh[m][k + 1];
        const float B  = (ysh[m][k + 1] - a) - h2 * (2.0f * c0 + c1) * (1.0f / 3.0f);
        const float C  = c0 * h2;
        const float D  = (c1 - c0) * h2 * (1.0f / 3.0f);

        const float ap = a + dlt * (B + dlt * (C + dlt * D));
        const float bp = B + dlt * (2.0f * C + 3.0f * D * dlt);
        const float cp = C + 3.0f * D * dlt;

        g_tab[m][j] = make_float4(ap, bp, cp, D);
    }
}

// ---------------------------------------------------------------------------
// K2: main evaluation
// ---------------------------------------------------------------------------
__device__ __forceinline__ void eval_lane(float xv, const float4* __restrict__ tab,
                                          float& acc)
{
    // t = (x+4) * 127/8 + 64  (pad offset folded in: 4*15.875 + 64 = 127.5)
    const float t = __fmaf_rn(xv, 15.875f, 127.5f);
    const int   i = __float2int_rd(t);              // floor — pads handle range
    const float u = t - __int2float_rn(i);          // u in [0,1)
    const float4 cf = tab[i];
    acc += __fmaf_rn(u, __fmaf_rn(u, __fmaf_rn(u, cf.w, cf.z), cf.y), cf.x);
}

__global__ void __launch_bounds__(NTHREADS) eval_kernel(const float4* __restrict__ x4)
{
    __shared__ float4 tab[TABN];

    // slab (bs,f) = 65536 elems = 4 blocks; marginal index = slab & 7
    const int m = (blockIdx.x >> 2) & 7;
    tab[threadIdx.x] = g_tab[m][threadIdx.x];
    __syncthreads();

    const float4* p = x4 + (size_t)blockIdx.x * F4_PER_BLOCK + threadIdx.x;

    float a0 = 0.0f, a1 = 0.0f, a2 = 0.0f, a3 = 0.0f;
#pragma unroll 4
    for (int it = 0; it < F4_PER_BLOCK / NTHREADS; ++it) {
        const float4 v = p[it * NTHREADS];
        eval_lane(v.x, tab, a0);
        eval_lane(v.y, tab, a1);
        eval_lane(v.z, tab, a2);
        eval_lane(v.w, tab, a3);
    }

    float s = (a0 + a1) + (a2 + a3);
#pragma unroll
    for (int o = 16; o > 0; o >>= 1)
        s += __shfl_xor_sync(0xFFFFFFFFu, s, o);

    __shared__ float wsum[NTHREADS / 32];
    if ((threadIdx.x & 31) == 0)
        wsum[threadIdx.x >> 5] = s;
    __syncthreads();

    if (threadIdx.x == 0) {
        float t = 0.0f;
#pragma unroll
        for (int w = 0; w < NTHREADS / 32; ++w)
            t += wsum[w];
        g_part[blockIdx.x] = t;
    }
}

// ---------------------------------------------------------------------------
// K3: deterministic final reduction
// ---------------------------------------------------------------------------
__global__ void reduce_kernel(float* __restrict__ out)
{
    __shared__ float sh[NTHREADS];
    float s = 0.0f;
    for (int i = threadIdx.x; i < EVAL_BLOCKS; i += NTHREADS)
        s += g_part[i];
    sh[threadIdx.x] = s;
    __syncthreads();
#pragma unroll
    for (int st = NTHREADS / 2; st > 0; st >>= 1) {
        if (threadIdx.x < st)
            sh[threadIdx.x] += sh[threadIdx.x + st];
        __syncthreads();
    }
    if (threadIdx.x == 0)
        out[0] = sh[0];
}

// ---------------------------------------------------------------------------
extern "C" void kernel_launch(void* const* d_in, const int* in_sizes, int n_in,
                              void* d_out, int out_size)
{
    const float* x     = (const float*)d_in[0];        // (32,8,256,256) fp32
    const float* nodal = (const float*)d_in[1];        // (8,128) fp32
    float* out = (float*)d_out;

    coef_kernel<<<1, NTHREADS>>>(nodal);
    eval_kernel<<<EVAL_BLOCKS, NTHREADS>>>((const float4*)x);
    reduce_kernel<<<1, NTHREADS>>>(out);
}

// round 2
// speedup vs baseline: 1.2385x; 1.2385x over previous
#include <cuda_runtime.h>

// NaturalCubicSplinePotential — GB300 sm_103a
//
// R1 change: coef_kernel rewritten from serial Thomas (19.2us, 8 active threads)
// to parallel cyclic reduction (PCR): 1024 threads = 8 marginals x 128 eqs,
// 7 elimination steps. Predicted <=3us.
//
//  K1 coef_kernel : PCR tridiagonal solve + PADDED per-marginal table of 256
//                   intervals of u-rescaled coefficients (t = (x+4)*127/8 + 64).
//                   Pad intervals hold exactly re-centered extrapolation cubics
//                   of the clamped boundary interval -> hot loop has NO clamp.
//  K2 eval_kernel : 1024 blocks x 256 threads, single wave. Block owns one
//                   contiguous 16384-elem chunk (1/4 of a (bs,f) slab -> one
//                   marginal per block). Per elem: FFMA + F2I + I2F + FADD +
//                   LDS.128 + 3 FFMA + FADD.
//  K3 reduce      : deterministic tree reduce of 1024 partials -> d_out[0].

#define NM 8
#define NN 128
#define TABN 256          // padded table entries per marginal
#define PADL 64           // pad below interval 0
#define EVAL_BLOCKS 1024
#define F4_PER_BLOCK 4096 // 16384 elements per block
#define NTHREADS 256
#define COEF_THREADS 1024

__device__ float4 g_tab[NM][TABN];
__device__ float  g_part[EVAL_BLOCKS];

// ---------------------------------------------------------------------------
// K1: PCR spline-coefficient solve + padded table build (1024 threads)
// ---------------------------------------------------------------------------
__global__ void __launch_bounds__(COEF_THREADS) coef_kernel(const float* __restrict__ nodal)
{
    __shared__ float ysh[NM][NN];
    __shared__ float sa[NM][NN];
    __shared__ float sb[NM][NN];
    __shared__ float sc[NM][NN];
    __shared__ float sr[NM][NN];

    const int tid = threadIdx.x;           // 0..1023
    const int m   = tid >> 7;              // marginal
    const int i   = tid & 127;             // node index

    ysh[m][i] = nodal[tid];
    __syncthreads();

    // Interior system (i = 1..126):  c_{i-1} + 4 c_i + c_{i+1} = r_i, c_0=c_127=0
    const float inv_h2 = (127.0f / 8.0f) * (127.0f / 8.0f);
    const bool interior = (i >= 1) && (i <= 126);

    float a, b, c, r;
    if (interior) {
        a = (i == 1)   ? 0.0f : 1.0f;
        c = (i == 126) ? 0.0f : 1.0f;
        b = 4.0f;
        r = 3.0f * (ysh[m][i - 1] - 2.0f * ysh[m][i] + ysh[m][i + 1]) * inv_h2;
    } else {
        a = 0.0f; c = 0.0f; b = 1.0f; r = 0.0f;   // identity equation
    }
    sa[m][i] = a; sb[m][i] = b; sc[m][i] = c; sr[m][i] = r;
    __syncthreads();

    // 7 PCR steps: strides 1,2,4,...,64
#pragma unroll
    for (int k = 1; k < 128; k <<= 1) {
        const int il = i - k;
        const int iu = i + k;
        float am, bm, cm, rm, ap, bp, cp, rp;
        if (interior && il >= 1) {
            am = sa[m][il]; bm = sb[m][il]; cm = sc[m][il]; rm = sr[m][il];
        } else { am = 0.0f; bm = 1.0f; cm = 0.0f; rm = 0.0f; }
        if (interior && iu <= 126) {
            ap = sa[m][iu]; bp = sb[m][iu]; cp = sc[m][iu]; rp = sr[m][iu];
        } else { ap = 0.0f; bp = 1.0f; cp = 0.0f; rp = 0.0f; }

        const float alpha = a / bm;
        const float gamma = c / bp;
        const float bn = b - alpha * cm - gamma * ap;
        const float an = -alpha * am;
        const float cn = -gamma * cp;
        const float rn = r - alpha * rm - gamma * rp;
        __syncthreads();
        a = an; b = bn; c = cn; r = rn;
        sa[m][i] = a; sb[m][i] = b; sc[m][i] = c; sr[m][i] = r;
        __syncthreads();
    }

    const float cval = interior ? (r / b) : 0.0f;
    sa[m][i] = cval;                       // reuse sa as csh
    __syncthreads();

    // Build padded, u-rescaled table.
    // In-range interval k: P(u) = A + B u + C u^2 + D u^3, u = (x - node_k)/h
    //   A = y_k
    //   B = (y_{k+1}-y_k) - h^2 (2 c_k + c_{k+1})/3
    //   C = c_k h^2
    //   D = (c_{k+1}-c_k) h^2 / 3
    // Pad entry for raw interval it (clamped to k): shift by Delta = it - k.
    const float h  = 8.0f / 127.0f;
    const float h2 = h * h;
    for (int e = tid; e < NM * TABN; e += COEF_THREADS) {
        const int mm = e >> 8;
        const int j  = e & 255;
        const int it = j - PADL;
        const int k  = min(max(it, 0), 126);
        const float dlt = (float)(it - k);

        const float A  = ysh[mm][k];
        const float c0 = sa[mm][k];
        const float c1 = sa[mm][k + 1];
        const float B  = (ysh[mm][k + 1] - A) - h2 * (2.0f * c0 + c1) * (1.0f / 3.0f);
        const float C  = c0 * h2;
        const float D  = (c1 - c0) * h2 * (1.0f / 3.0f);

        const float ap2 = A + dlt * (B + dlt * (C + dlt * D));
        const float bp2 = B + dlt * (2.0f * C + 3.0f * D * dlt);
        const float cp2 = C + 3.0f * D * dlt;

        g_tab[mm][j] = make_float4(ap2, bp2, cp2, D);
    }
}

// ---------------------------------------------------------------------------
// K2: main evaluation
// ---------------------------------------------------------------------------
__device__ __forceinline__ void eval_lane(float xv, const float4* __restrict__ tab,
                                          float& acc)
{
    // t = (x+4) * 127/8 + 64  (pad offset folded in: 4*15.875 + 64 = 127.5)
    const float t = __fmaf_rn(xv, 15.875f, 127.5f);
    const int   i = __float2int_rd(t);              // floor — pads absorb range
    const float u = t - __int2float_rn(i);          // u in [0,1)
    const float4 cf = tab[i];
    acc += __fmaf_rn(u, __fmaf_rn(u, __fmaf_rn(u, cf.w, cf.z), cf.y), cf.x);
}

__global__ void __launch_bounds__(NTHREADS) eval_kernel(const float4* __restrict__ x4)
{
    __shared__ float4 tab[TABN];

    // slab (bs,f) = 65536 elems = 4 blocks; marginal index = slab & 7
    const int m = (blockIdx.x >> 2) & 7;
    tab[threadIdx.x] = g_tab[m][threadIdx.x];
    __syncthreads();

    const float4* p = x4 + (size_t)blockIdx.x * F4_PER_BLOCK + threadIdx.x;

    float a0 = 0.0f, a1 = 0.0f, a2 = 0.0f, a3 = 0.0f;
#pragma unroll 4
    for (int it = 0; it < F4_PER_BLOCK / NTHREADS; ++it) {
        const float4 v = p[it * NTHREADS];
        eval_lane(v.x, tab, a0);
        eval_lane(v.y, tab, a1);
        eval_lane(v.z, tab, a2);
        eval_lane(v.w, tab, a3);
    }

    float s = (a0 + a1) + (a2 + a3);
#pragma unroll
    for (int o = 16; o > 0; o >>= 1)
        s += __shfl_xor_sync(0xFFFFFFFFu, s, o);

    __shared__ float wsum[NTHREADS / 32];
    if ((threadIdx.x & 31) == 0)
        wsum[threadIdx.x >> 5] = s;
    __syncthreads();

    if (threadIdx.x == 0) {
        float t = 0.0f;
#pragma unroll
        for (int w = 0; w < NTHREADS / 32; ++w)
            t += wsum[w];
        g_part[blockIdx.x] = t;
    }
}

// ---------------------------------------------------------------------------
// K3: deterministic final reduction
// ---------------------------------------------------------------------------
__global__ void reduce_kernel(float* __restrict__ out)
{
    __shared__ float sh[NTHREADS];
    float s = 0.0f;
    for (int i = threadIdx.x; i < EVAL_BLOCKS; i += NTHREADS)
        s += g_part[i];
    sh[threadIdx.x] = s;
    __syncthreads();
#pragma unroll
    for (int st = NTHREADS / 2; st > 0; st >>= 1) {
        if (threadIdx.x < st)
            sh[threadIdx.x] += sh[threadIdx.x + st];
        __syncthreads();
    }
    if (threadIdx.x == 0)
        out[0] = sh[0];
}

// ---------------------------------------------------------------------------
extern "C" void kernel_launch(void* const* d_in, const int* in_sizes, int n_in,
                              void* d_out, int out_size)
{
    const float* x     = (const float*)d_in[0];        // (32,8,256,256) fp32
    const float* nodal = (const float*)d_in[1];        // (8,128) fp32
    float* out = (float*)d_out;

    coef_kernel<<<1, COEF_THREADS>>>(nodal);
    eval_kernel<<<EVAL_BLOCKS, NTHREADS>>>((const float4*)x);
    reduce_kernel<<<1, NTHREADS>>>(out);
}

// round 4
// speedup vs baseline: 1.6547x; 1.3361x over previous
#include <cuda_runtime.h>

// NaturalCubicSplinePotential — GB300 sm_103a
//
// R2: coef kernel ELIMINATED. The [1,4,1] tridiagonal system is constant, so
// its inverse has a closed form (theta = arccosh(2), lambda = 2+sqrt(3)):
//   Ainv[i][j] = (-1)^{i+j} lam^{mi-mx-1} (1-lam^{-2 mi})(1-lam^{-2(M-mx)}) / (1-lam^{-2})
// with M=127. Weights decay lam^{-d}; truncate at |i-j|<=15 (error ~2e-10).
// Every eval block rebuilds its marginal's padded table in a ~0.5us prologue
// (runs in parallel across all SMs instead of a 10.8us serial grid=1 kernel).
//
//  K1 eval_kernel : prologue (31-tap conv solve + padded 256-entry table),
//                   then 16384 contiguous elems/block, single wave.
//  K2 reduce      : deterministic tree reduce of 1024 partials -> d_out[0].

#define NM 8
#define NN 128
#define TABN 256          // padded table entries per marginal
#define PADL 64           // pad below interval 0
#define EVAL_BLOCKS 1024
#define F4_PER_BLOCK 4096 // 16384 elements per block
#define NTHREADS 256
#define CONV_R 15         // truncation radius of inverse-matrix convolution

__device__ float g_part[EVAL_BLOCKS];

// lam = 2+sqrt(3); log2(lam) = 1.89996863
#define LOG2_LAM 1.89996863f
#define INV_D0   1.07735027f   // 1/(1-lam^-2)

// ---------------------------------------------------------------------------
// K1: fused table-build + evaluation
// ---------------------------------------------------------------------------
__device__ __forceinline__ void eval_lane(float xv, const float4* __restrict__ tab,
                                          float& acc)
{
    // t = (x+4) * 127/8 + 64  (pad offset folded in: 4*15.875 + 64 = 127.5)
    const float t = __fmaf_rn(xv, 15.875f, 127.5f);
    const int   i = __float2int_rd(t);              // floor — pads absorb range
    const float u = t - __int2float_rn(i);          // u in [0,1)
    const float4 cf = tab[i];
    acc += __fmaf_rn(u, __fmaf_rn(u, __fmaf_rn(u, cf.w, cf.z), cf.y), cf.x);
}

__global__ void __launch_bounds__(NTHREADS) eval_kernel(const float4* __restrict__ x4,
                                                        const float* __restrict__ nodal)
{
    __shared__ float4 tab[TABN];
    __shared__ float  ysh[NN];
    __shared__ float  pw[256];           // pw[k] = lam^{-k}
    __shared__ float  srsh[NN + 2 * (CONV_R + 1)]; // padded (-1)^j * r_j
    __shared__ float  csh[NN];

    const int tid = threadIdx.x;
    // slab (bs,f) = 65536 elems = 4 blocks; marginal index = slab & 7
    const int m = (blockIdx.x >> 2) & 7;

    // ---- prologue: spline solve + table build --------------------------------
    if (tid < NN)
        ysh[tid] = nodal[m * NN + tid];
    pw[tid] = exp2f(-LOG2_LAM * (float)tid);
    if (tid < NN + 2 * (CONV_R + 1))
        srsh[tid] = 0.0f;
    __syncthreads();

    // rhs with sign fold: srsh[PAD + j] = (-1)^j * 3*(y_{j-1}-2y_j+y_{j+1})/h^2
    const float inv_h2 = (127.0f / 8.0f) * (127.0f / 8.0f);
    if (tid >= 1 && tid <= 126) {
        float r = 3.0f * (ysh[tid - 1] - 2.0f * ysh[tid] + ysh[tid + 1]) * inv_h2;
        srsh[(CONV_R + 1) + tid] = (tid & 1) ? -r : r;
    }
    __syncthreads();

    // c_i = (-1)^i * invD0 * sum_dj pw[|dj|+1]*(1-pw[2mi])*(1-pw[2(127-mx)]) * srsh[i+dj]
    if (tid < NN) {
        const int i = tid;
        float c = 0.0f;
        if (i >= 1 && i <= 126) {
#pragma unroll
            for (int dj = -CONV_R; dj <= CONV_R; ++dj) {
                const int j  = i + dj;
                const int jc = min(max(j, 1), 126);      // clamp (value is 0 outside)
                const int mi = min(i, jc);
                const int mx = max(i, jc);
                const float w = pw[(dj < 0 ? -dj : dj) + 1]
                              * (1.0f - pw[2 * mi])
                              * (1.0f - pw[2 * (127 - mx)]);
                c = __fmaf_rn(w, srsh[(CONV_R + 1) + j], c);
            }
            c *= INV_D0;
            if (i & 1) c = -c;
        }
        csh[i] = c;
    }
    __syncthreads();

    // Padded, u-rescaled table. In-range interval k:
    //   P(u) = A + B u + C u^2 + D u^3, u = (x - node_k)/h
    //   A = y_k ; B = (y_{k+1}-y_k) - h^2(2c_k+c_{k+1})/3 ; C = c_k h^2 ;
    //   D = (c_{k+1}-c_k) h^2/3
    // Pad entry for raw interval it (clamped to k): recenter by Delta = it-k.
    {
        const float h  = 8.0f / 127.0f;
        const float h2 = h * h;
        const int j  = tid;
        const int it = j - PADL;
        const int k  = min(max(it, 0), 126);
        const float dlt = (float)(it - k);

        const float A  = ysh[k];
        const float c0 = csh[k];
        const float c1 = csh[k + 1];
        const float B  = (ysh[k + 1] - A) - h2 * (2.0f * c0 + c1) * (1.0f / 3.0f);
        const float C  = c0 * h2;
        const float D  = (c1 - c0) * h2 * (1.0f / 3.0f);

        const float ap = A + dlt * (B + dlt * (C + dlt * D));
        const float bp = B + dlt * (2.0f * C + 3.0f * D * dlt);
        const float cp = C + 3.0f * D * dlt;

        tab[j] = make_float4(ap, bp, cp, D);
    }
    __syncthreads();

    // ---- main evaluation loop ------------------------------------------------
    const float4* p = x4 + (size_t)blockIdx.x * F4_PER_BLOCK + threadIdx.x;

    float a0 = 0.0f, a1 = 0.0f, a2 = 0.0f, a3 = 0.0f;
#pragma unroll 4
    for (int it = 0; it < F4_PER_BLOCK / NTHREADS; ++it) {
        const float4 v = p[it * NTHREADS];
        eval_lane(v.x, tab, a0);
        eval_lane(v.y, tab, a1);
        eval_lane(v.z, tab, a2);
        eval_lane(v.w, tab, a3);
    }

    float s = (a0 + a1) + (a2 + a3);
#pragma unroll
    for (int o = 16; o > 0; o >>= 1)
        s += __shfl_xor_sync(0xFFFFFFFFu, s, o);

    __shared__ float wsum[NTHREADS / 32];
    if ((threadIdx.x & 31) == 0)
        wsum[threadIdx.x >> 5] = s;
    __syncthreads();

    if (threadIdx.x == 0) {
        float t = 0.0f;
#pragma unroll
        for (int w = 0; w < NTHREADS / 32; ++w)
            t += wsum[w];
        g_part[blockIdx.x] = t;
    }
}

// ---------------------------------------------------------------------------
// K2: deterministic final reduction
// ---------------------------------------------------------------------------
__global__ void reduce_kernel(float* __restrict__ out)
{
    __shared__ float sh[NTHREADS];
    float s = 0.0f;
    for (int i = threadIdx.x; i < EVAL_BLOCKS; i += NTHREADS)
        s += g_part[i];
    sh[threadIdx.x] = s;
    __syncthreads();
#pragma unroll
    for (int st = NTHREADS / 2; st > 0; st >>= 1) {
        if (threadIdx.x < st)
            sh[threadIdx.x] += sh[threadIdx.x + st];
        __syncthreads();
    }
    if (threadIdx.x == 0)
        out[0] = sh[0];
}

// ---------------------------------------------------------------------------
extern "C" void kernel_launch(void* const* d_in, const int* in_sizes, int n_in,
                              void* d_out, int out_size)
{
    const float* x     = (const float*)d_in[0];        // (32,8,256,256) fp32
    const float* nodal = (const float*)d_in[1];        // (8,128) fp32
    float* out = (float*)d_out;

    eval_kernel<<<EVAL_BLOCKS, NTHREADS>>>((const float4*)x, nodal);
    reduce_kernel<<<1, NTHREADS>>>(out);
}